// round 13
// baseline (speedup 1.0000x reference)
#include <cuda_runtime.h>
#include <cuda_bf16.h>
#include <math.h>
#include <stdint.h>

// Problem constants
#define B_  2
#define S_  2048
#define HID 2048
#define NH  16
#define NKV 4
#define DH  128
#define MROWS (B_ * S_)        // 4096
#define EPS 1e-6f

// packed QKV col layout: [ Q(0..2047) | K(2048..2559) | V(2560..3071) ]
#define QKVS 3072
#define KOFF 2048
#define VOFF 2560

// 1/sqrt(DH) * log2(e): folded into Q during rmsrope; softmax uses exp2f.
#define SCL2E (0.08838834764831845f * 1.4426950408889634f)

// K-dim fragment interleave: within each 8-group, q -> 2*(q&3) + (q>>2).
__device__ __host__ __forceinline__ int perm8(int q) { return 2 * (q & 3) + (q >> 2); }

// ---------------- scratch ----------------
__device__ float g_X   [(size_t)MROWS * HID];        // Xr (K-permuted input)
__device__ float g_QKV [(size_t)MROWS * QKVS];       // packed Q|K|V (normal layout)
__device__ float g_Qp  [(size_t)MROWS * HID];        // Q, rms+rope'd, d-permuted, prescaled
__device__ float g_Kp  [(size_t)MROWS * NKV * DH];   // K, rms+rope'd, d-permuted
__device__ float g_Vt  [(size_t)B_ * NKV * DH * S_]; // [b][kvh][d][s'], s-permuted, tf32
__device__ float g_O   [(size_t)MROWS * NH * DH];    // flash out, d-permuted
__device__ float g_WqkvT[(size_t)QKVS * HID];        // [N=3072][K=2048], K-permuted
__device__ float g_WoT [(size_t)NH * DH * HID];      // [N=2048][K=2048], K-permuted

// ---------------- helpers ----------------
__device__ __forceinline__ uint32_t smem_u32(const void* p) {
    uint32_t a;
    asm("{ .reg .u64 t; cvta.to.shared.u64 t, %1; cvt.u32.u64 %0, t; }" : "=r"(a) : "l"(p));
    return a;
}
__device__ __forceinline__ float tf32r(float x) {
    uint32_t r;
    asm("cvt.rna.tf32.f32 %0, %1;" : "=r"(r) : "f"(x));
    return __uint_as_float(r);
}
#define CP_ASYNC16(sdst, gsrc) \
    asm volatile("cp.async.cg.shared.global [%0], [%1], 16;" :: "r"(sdst), "l"(gsrc))
#define CP_COMMIT() asm volatile("cp.async.commit_group;" ::: "memory")
#define CP_WAIT(n)  asm volatile("cp.async.wait_group %0;" :: "n"(n) : "memory")

__device__ __forceinline__ void mma_tf32(float& c0, float& c1, float& c2, float& c3,
                                         uint32_t a0, uint32_t a1, uint32_t a2, uint32_t a3,
                                         uint32_t b0, uint32_t b1) {
    asm volatile(
        "mma.sync.aligned.m16n8k8.row.col.f32.tf32.tf32.f32 "
        "{%0,%1,%2,%3}, {%4,%5,%6,%7}, {%8,%9}, {%0,%1,%2,%3};"
        : "+f"(c0), "+f"(c1), "+f"(c2), "+f"(c3)
        : "r"(a0), "r"(a1), "r"(a2), "r"(a3), "r"(b0), "r"(b1));
}

// ---------------- X: tf32 round + K-dim interleave ----------------
__global__ void __launch_bounds__(256) xperm_tf32_kernel(float* __restrict__ dst,
                                                         const float* __restrict__ src,
                                                         size_t n8) {
    for (size_t i = blockIdx.x * blockDim.x + threadIdx.x; i < n8;
         i += (size_t)gridDim.x * blockDim.x) {
        float4 lo = ((const float4*)src)[i * 2];
        float4 hi = ((const float4*)src)[i * 2 + 1];
        float4 o0 = make_float4(tf32r(lo.x), tf32r(hi.x), tf32r(lo.y), tf32r(hi.y));
        float4 o1 = make_float4(tf32r(lo.z), tf32r(hi.z), tf32r(lo.w), tf32r(hi.w));
        ((float4*)dst)[i * 2]     = o0;
        ((float4*)dst)[i * 2 + 1] = o1;
    }
}

// ---------------- transpose + tf32 round + K-permute ----------------
__global__ void __launch_bounds__(256) transpose_tf32_kernel(float* __restrict__ dst,
                                                             const float* __restrict__ src,
                                                             int R, int C) {
    __shared__ float t[32][33];
    int bx = blockIdx.x * 32;
    int by = blockIdx.y * 32;
    int tx = threadIdx.x, ty = threadIdx.y;
#pragma unroll
    for (int i = 0; i < 4; i++)
        t[ty + i * 8][tx] = src[(size_t)(by + ty + i * 8) * C + bx + tx];
    __syncthreads();
    int px = (tx & 24) + perm8(tx & 7);
#pragma unroll
    for (int i = 0; i < 4; i++)
        dst[(size_t)(bx + ty + i * 8) * R + by + px] = tf32r(t[tx][ty + i * 8]);
}

// ---------------- V transpose from packed QKV -> g_Vt [b][kvh][d][s'] (tf32) ----------------
__global__ void __launch_bounds__(256) vtrans_kernel(float* __restrict__ dst,
                                                     const float* __restrict__ src) {
    __shared__ float t[32][33];
    const int bz = blockIdx.z;              // b*NKV + kvh
    const int b = bz >> 2, kvh = bz & 3;
    const int s0 = blockIdx.x * 32, d0 = blockIdx.y * 32;
    const int tx = threadIdx.x, ty = threadIdx.y;   // 32 x 8
#pragma unroll
    for (int i = 0; i < 4; i++)
        t[ty + i * 8][tx] =
            src[(size_t)(b * S_ + s0 + ty + i * 8) * QKVS + VOFF + kvh * DH + d0 + tx];
    __syncthreads();
    int px = (tx & 24) + perm8(tx & 7);
#pragma unroll
    for (int i = 0; i < 4; i++)
        dst[((size_t)bz * DH + d0 + ty + i * 8) * S_ + s0 + px] = tf32r(t[tx][ty + i * 8]);
}

// ---------------- tf32 mma.sync GEMM (K-permuted operands, LDS.64 fragments) ----------------
#define GK      2048
#define GM_BM   128
#define GM_BN   128
#define GM_BK   16
#define GM_LDS  24
#define GM_NST  3
#define GM_NIT  (GK / GM_BK)
#define GM_STAGE_FLOATS (2 * 128 * GM_LDS)   // 6144
#define GM_SMEM_BYTES (GM_NST * GM_STAGE_FLOATS * 4)   // 73728

__device__ __forceinline__ void gm_load_stage(uint32_t sA, uint32_t sB,
                                              const float* __restrict__ Atile,
                                              const float* __restrict__ Btile,
                                              int tid) {
#pragma unroll
    for (int i = 0; i < 2; i++) {
        int idx = i * 256 + tid;
        int r = idx >> 2, c = idx & 3;
        CP_ASYNC16(sA + (uint32_t)(r * (GM_LDS * 4) + c * 16),
                   Atile + (size_t)r * GK + c * 4);
    }
#pragma unroll
    for (int i = 0; i < 2; i++) {
        int idx = i * 256 + tid;
        int r = idx >> 2, c = idx & 3;
        CP_ASYNC16(sB + (uint32_t)(r * (GM_LDS * 4) + c * 16),
                   Btile + (size_t)r * GK + c * 4);
    }
    CP_COMMIT();
}

__global__ void __launch_bounds__(256, 1) gemm_tf32mma_kernel(
    const float* __restrict__ A, const float* __restrict__ Bt,
    float* __restrict__ C, int M, int N)
{
    extern __shared__ float gsm[];
    const uint32_t sbase = smem_u32(gsm);
    const int tid = threadIdx.x;
    const int wid = tid >> 5, lid = tid & 31;
    const int wm = wid >> 1, wn = wid & 1;
    const int gid = lid >> 2, tig = lid & 3;
    const int bm = blockIdx.y * GM_BM;
    const int bn = blockIdx.x * GM_BN;

    float acc[2][8][4];
#pragma unroll
    for (int mt = 0; mt < 2; mt++)
#pragma unroll
        for (int nt = 0; nt < 8; nt++)
#pragma unroll
            for (int q = 0; q < 4; q++) acc[mt][nt][q] = 0.f;

    const float* Abase = A + (size_t)bm * GK;
    const float* Bbase = Bt + (size_t)bn * GK;

    uint32_t stA[GM_NST], stB[GM_NST];
#pragma unroll
    for (int s = 0; s < GM_NST; s++) {
        stA[s] = sbase + (uint32_t)(s * GM_STAGE_FLOATS * 4);
        stB[s] = stA[s] + 128u * GM_LDS * 4u;
    }

    gm_load_stage(stA[0], stB[0], Abase, Bbase, tid);
    gm_load_stage(stA[1], stB[1], Abase + GM_BK, Bbase + GM_BK, tid);

    for (int it = 0; it < GM_NIT; it++) {
        CP_WAIT(1);
        __syncthreads();

        const int ki = it + 2;
        if (ki < GM_NIT) {
            const int b = ki % GM_NST;
            gm_load_stage(stA[b], stB[b], Abase + ki * GM_BK, Bbase + ki * GM_BK, tid);
        }

        const int s = it % GM_NST;
        const float* As0 = gsm + (size_t)s * GM_STAGE_FLOATS;
        const float* Bs0 = As0 + 128 * GM_LDS;

#pragma unroll
        for (int k0 = 0; k0 < GM_BK; k0 += 8) {
            uint32_t af[2][4];
#pragma unroll
            for (int mt = 0; mt < 2; mt++) {
                int r = wm * 32 + mt * 16 + gid;
                float2 aA = *(const float2*)(As0 + r * GM_LDS + k0 + 2 * tig);
                float2 aB = *(const float2*)(As0 + (r + 8) * GM_LDS + k0 + 2 * tig);
                af[mt][0] = __float_as_uint(aA.x);
                af[mt][1] = __float_as_uint(aB.x);
                af[mt][2] = __float_as_uint(aA.y);
                af[mt][3] = __float_as_uint(aB.y);
            }
#pragma unroll
            for (int nt = 0; nt < 8; nt++) {
                int rn = wn * 64 + nt * 8 + gid;
                float2 bv = *(const float2*)(Bs0 + rn * GM_LDS + k0 + 2 * tig);
#pragma unroll
                for (int mt = 0; mt < 2; mt++)
                    mma_tf32(acc[mt][nt][0], acc[mt][nt][1], acc[mt][nt][2], acc[mt][nt][3],
                             af[mt][0], af[mt][1], af[mt][2], af[mt][3],
                             __float_as_uint(bv.x), __float_as_uint(bv.y));
            }
        }
    }

#pragma unroll
    for (int mt = 0; mt < 2; mt++) {
        int r0 = bm + wm * 32 + mt * 16 + gid;
#pragma unroll
        for (int nt = 0; nt < 8; nt++) {
            int c = bn + wn * 64 + nt * 8 + tig * 2;
            *(float2*)(C + (size_t)r0 * N + c) = make_float2(acc[mt][nt][0], acc[mt][nt][1]);
            *(float2*)(C + (size_t)(r0 + 8) * N + c) = make_float2(acc[mt][nt][2], acc[mt][nt][3]);
        }
    }
}

// ---------------- fused RMSNorm + RoPE (reads packed QKV; writes d-permuted) ----------------
__global__ void __launch_bounds__(128) rmsrope_kernel(
    const float* __restrict__ inbuf, float* __restrict__ outbuf,
    const float* __restrict__ w,
    const float* __restrict__ cosb, const float* __restrict__ sinb, int nheads,
    float oscale, int in_hoff, int outstride)
{
    const int bh  = blockIdx.x;
    const int row = bh / nheads;
    const int h   = bh - row * nheads;
    const int s   = row & (S_ - 1);
    const int d   = threadIdx.x;

    const float* p = inbuf + (size_t)row * QKVS + in_hoff + h * DH;
    float v = p[d];

    float ss = v * v;
#pragma unroll
    for (int o = 16; o > 0; o >>= 1) ss += __shfl_xor_sync(0xffffffffu, ss, o);
    __shared__ float sh[4];
    if ((d & 31) == 0) sh[d >> 5] = ss;
    __syncthreads();
    float tot = sh[0] + sh[1] + sh[2] + sh[3];
    float inv = rsqrtf(tot * (1.0f / DH) + EPS);

    int pd = d ^ 64;
    float pv  = p[pd];
    float nv  = w[d]  * v  * inv;
    float npv = w[pd] * pv * inv;
    float c  = cosb[(size_t)s * DH + d];
    float sn = sinb[(size_t)s * DH + d];
    float out = nv * c + ((d < 64) ? -npv : npv) * sn;

    int dp = (d & ~7) + perm8(d & 7);
    outbuf[(size_t)row * outstride + h * DH + dp] = tf32r(out * oscale);
}

// ---------------- tensor-core flash attention v5 ----------------
// BM=256 q rows, BN=64 kv cols, 512 threads = 16 warps x 16 rows.
// Single-buffered K/V with split-wait overlap:
//   V load hides behind S-phase+softmax; next K issues during PV; next V after PV.
#define F5_FKP 136
#define F5_FVP 72
#define F5_K_OFF (256 * F5_FKP)               // 34816 floats
#define F5_V_OFF (F5_K_OFF + 64 * F5_FKP)     // 43520 floats
#define F5_FLOATS (F5_V_OFF + 128 * F5_FVP)   // 52736 floats
#define F5_BYTES (F5_FLOATS * 4)              // 210944 bytes

__global__ void __launch_bounds__(512, 1) flash_tc5_kernel(
    const float* __restrict__ Qp, const float* __restrict__ Kp,
    const float* __restrict__ Vt, float* __restrict__ Og)
{
    extern __shared__ float fsm[];
    const uint32_t sb = smem_u32(fsm);

    const int qt  = (int)gridDim.x - 1 - (int)blockIdx.x;   // long blocks first
    const int h   = blockIdx.y;
    const int b   = blockIdx.z;
    const int kvh = h >> 2;
    const int tid = threadIdx.x;
    const int wid = tid >> 5, lid = tid & 31;
    const int gid = lid >> 2, tig = lid & 3;

    const int r1loc = wid * 16 + gid;      // 0..255
    const int r2loc = r1loc + 8;
    const int r1g = qt * 256 + r1loc;
    const int r2g = r1g + 8;

    const float* Kbase  = Kp + (size_t)(b * S_) * (NKV * DH) + (size_t)kvh * DH;
    const float* Vtbase = Vt + ((size_t)(b * NKV + kvh) * DH) * S_;

    // group 1: Q tile (256 rows x 32 chunks) + K tile 0 (64 x 32 chunks)
    {
        const float* Qb = Qp + (size_t)(b * S_ + qt * 256) * HID + (size_t)h * DH;
#pragma unroll
        for (int t = 0; t < 16; t++) {
            int i = tid + t * 512;
            int m = i >> 5, c = i & 31;
            CP_ASYNC16(sb + (uint32_t)((m * F5_FKP + c * 4) * 4),
                       Qb + (size_t)m * HID + c * 4);
        }
    }
#pragma unroll
    for (int t = 0; t < 4; t++) {
        int i = tid + t * 512;
        int n = i >> 5, c = i & 31;
        CP_ASYNC16(sb + (uint32_t)((F5_K_OFF + n * F5_FKP + c * 4) * 4),
                   Kbase + (size_t)n * (NKV * DH) + c * 4);
    }
    CP_COMMIT();
    // group 2: V tile 0 (128 d x 16 chunks)
#pragma unroll
    for (int t = 0; t < 4; t++) {
        int i = tid + t * 512;
        int d = i >> 4, c = i & 15;
        CP_ASYNC16(sb + (uint32_t)((F5_V_OFF + d * F5_FVP + c * 4) * 4),
                   Vtbase + (size_t)d * S_ + c * 4);
    }
    CP_COMMIT();

    float oacc[16][4];
#pragma unroll
    for (int db = 0; db < 16; db++)
#pragma unroll
        for (int q = 0; q < 4; q++) oacc[db][q] = 0.f;
    float m1 = -1e30f, m2 = -1e30f, l1 = 0.f, l2 = 0.f;

    const float* Qsb = fsm;
    const float* Ksb = fsm + F5_K_OFF;
    const float* Vsb = fsm + F5_V_OFF;

    const int ntiles = 4 * qt + 4;
    for (int j = 0; j < ntiles; j++) {
        CP_WAIT(1);                 // K_j (and Q) complete; V_j may still be in flight
        __syncthreads();

        // S = Q @ K^T
        float sacc[8][4];
#pragma unroll
        for (int nb = 0; nb < 8; nb++)
#pragma unroll
            for (int q = 0; q < 4; q++) sacc[nb][q] = 0.f;

#pragma unroll
        for (int ks = 0; ks < 16; ks++) {
            int k0 = ks * 8;
            float2 qa = *(const float2*)(Qsb + r1loc * F5_FKP + k0 + 2 * tig);
            float2 qb = *(const float2*)(Qsb + r2loc * F5_FKP + k0 + 2 * tig);
            uint32_t a0 = __float_as_uint(qa.x);
            uint32_t a1 = __float_as_uint(qb.x);
            uint32_t a2 = __float_as_uint(qa.y);
            uint32_t a3 = __float_as_uint(qb.y);
#pragma unroll
            for (int nb = 0; nb < 8; nb++) {
                float2 kv2 = *(const float2*)(Ksb + (nb * 8 + gid) * F5_FKP + k0 + 2 * tig);
                mma_tf32(sacc[nb][0], sacc[nb][1], sacc[nb][2], sacc[nb][3],
                         a0, a1, a2, a3,
                         __float_as_uint(kv2.x), __float_as_uint(kv2.y));
            }
        }

        // causal mask (warp-uniform trigger)
        if (j * 64 + 63 > qt * 256 + wid * 16) {
#pragma unroll
            for (int nb = 0; nb < 8; nb++) {
                int c0g = j * 64 + nb * 8 + tig * 2;
                if (c0g > r1g)     sacc[nb][0] = -1e30f;
                if (c0g + 1 > r1g) sacc[nb][1] = -1e30f;
                if (c0g > r2g)     sacc[nb][2] = -1e30f;
                if (c0g + 1 > r2g) sacc[nb][3] = -1e30f;
            }
        }

        // row max over quad
        float mx1 = -1e30f, mx2 = -1e30f;
#pragma unroll
        for (int nb = 0; nb < 8; nb++) {
            mx1 = fmaxf(mx1, fmaxf(sacc[nb][0], sacc[nb][1]));
            mx2 = fmaxf(mx2, fmaxf(sacc[nb][2], sacc[nb][3]));
        }
        mx1 = fmaxf(mx1, __shfl_xor_sync(0xffffffffu, mx1, 1));
        mx1 = fmaxf(mx1, __shfl_xor_sync(0xffffffffu, mx1, 2));
        mx2 = fmaxf(mx2, __shfl_xor_sync(0xffffffffu, mx2, 1));
        mx2 = fmaxf(mx2, __shfl_xor_sync(0xffffffffu, mx2, 2));

        float mn1 = fmaxf(m1, mx1), mn2 = fmaxf(m2, mx2);
        const bool changed = (mn1 != m1) | (mn2 != m2);
        const bool any_changed = __any_sync(0xffffffffu, changed);
        float f1 = 1.f, f2 = 1.f;
        if (any_changed) {
            f1 = exp2f(m1 - mn1);
            f2 = exp2f(m2 - mn2);
        }
        m1 = mn1; m2 = mn2;

        // probs + row sums
        float ls1 = 0.f, ls2 = 0.f;
#pragma unroll
        for (int nb = 0; nb < 8; nb++) {
            float p0 = tf32r(exp2f(sacc[nb][0] - mn1));
            float p1 = tf32r(exp2f(sacc[nb][1] - mn1));
            float p2 = tf32r(exp2f(sacc[nb][2] - mn2));
            float p3 = tf32r(exp2f(sacc[nb][3] - mn2));
            sacc[nb][0] = p0; sacc[nb][1] = p1;
            sacc[nb][2] = p2; sacc[nb][3] = p3;
            ls1 += p0 + p1;
            ls2 += p2 + p3;
        }
        ls1 += __shfl_xor_sync(0xffffffffu, ls1, 1);
        ls1 += __shfl_xor_sync(0xffffffffu, ls1, 2);
        ls2 += __shfl_xor_sync(0xffffffffu, ls2, 1);
        ls2 += __shfl_xor_sync(0xffffffffu, ls2, 2);

        if (any_changed) {
            l1 = l1 * f1 + ls1;
            l2 = l2 * f2 + ls2;
#pragma unroll
            for (int db = 0; db < 16; db++) {
                oacc[db][0] *= f1; oacc[db][1] *= f1;
                oacc[db][2] *= f2; oacc[db][3] *= f2;
            }
        } else {
            l1 += ls1;
            l2 += ls2;
        }

        CP_WAIT(0);                 // V_j complete; all warps done reading Ks (S-phase)
        __syncthreads();

        // issue next K tile into Ks (free now) — overlaps PV phase
        if (j + 1 < ntiles) {
#pragma unroll
            for (int t = 0; t < 4; t++) {
                int i = tid + t * 512;
                int n = i >> 5, c = i & 31;
                CP_ASYNC16(sb + (uint32_t)((F5_K_OFF + n * F5_FKP + c * 4) * 4),
                           Kbase + (size_t)((j + 1) * 64 + n) * (NKV * DH) + c * 4);
            }
            CP_COMMIT();
        }

        // O += P @ V  (A-frag from sacc via quad shfls)
        const int s2 = tig >> 1;
        const bool odd = (tig & 1);
#pragma unroll
        for (int ks = 0; ks < 8; ks++) {
            float e, o;
            e = __shfl_sync(0xffffffffu, sacc[ks][0], s2, 4);
            o = __shfl_sync(0xffffffffu, sacc[ks][1], s2, 4);
            float a0f = odd ? o : e;
            e = __shfl_sync(0xffffffffu, sacc[ks][0], s2 + 2, 4);
            o = __shfl_sync(0xffffffffu, sacc[ks][1], s2 + 2, 4);
            float a2f = odd ? o : e;
            e = __shfl_sync(0xffffffffu, sacc[ks][2], s2, 4);
            o = __shfl_sync(0xffffffffu, sacc[ks][3], s2, 4);
            float a1f = odd ? o : e;
            e = __shfl_sync(0xffffffffu, sacc[ks][2], s2 + 2, 4);
            o = __shfl_sync(0xffffffffu, sacc[ks][3], s2 + 2, 4);
            float a3f = odd ? o : e;

            uint32_t a0 = __float_as_uint(a0f);
            uint32_t a1 = __float_as_uint(a1f);
            uint32_t a2 = __float_as_uint(a2f);
            uint32_t a3 = __float_as_uint(a3f);
            int k0 = ks * 8;
#pragma unroll
            for (int db = 0; db < 16; db++) {
                float2 vv = *(const float2*)(Vsb + (db * 8 + gid) * F5_FVP + k0 + 2 * tig);
                mma_tf32(oacc[db][0], oacc[db][1], oacc[db][2], oacc[db][3],
                         a0, a1, a2, a3,
                         __float_as_uint(vv.x), __float_as_uint(vv.y));
            }
        }

        __syncthreads();            // all warps done reading Vs

        // issue next V tile into Vs — overlaps next iteration's S-phase
        if (j + 1 < ntiles) {
#pragma unroll
            for (int t = 0; t < 4; t++) {
                int i = tid + t * 512;
                int d = i >> 4, c = i & 15;
                CP_ASYNC16(sb + (uint32_t)((F5_V_OFF + d * F5_FVP + c * 4) * 4),
                           Vtbase + (size_t)d * S_ + (j + 1) * 64 + c * 4);
            }
            CP_COMMIT();
        }
    }

    // epilogue: normalize, tf32-round, write d-permuted (feeds K-permuted O-proj)
    const float inv1 = 1.0f / l1, inv2 = 1.0f / l2;
    const size_t obase = ((size_t)(b * S_ + qt * 256)) * (NH * DH) + (size_t)h * DH;
    const int p0 = perm8(2 * tig);
    const int p1 = perm8(2 * tig + 1);
#pragma unroll
    for (int db = 0; db < 16; db++) {
        float* o1p = Og + obase + (size_t)r1loc * (NH * DH) + db * 8;
        float* o2p = Og + obase + (size_t)r2loc * (NH * DH) + db * 8;
        o1p[p0] = tf32r(oacc[db][0] * inv1);
        o1p[p1] = tf32r(oacc[db][1] * inv1);
        o2p[p0] = tf32r(oacc[db][2] * inv2);
        o2p[p1] = tf32r(oacc[db][3] * inv2);
    }
}

// ---------------- launch ----------------
extern "C" void kernel_launch(void* const* d_in, const int* in_sizes, int n_in,
                              void* d_out, int out_size)
{
    const float* X    = (const float*)d_in[0];
    // d_in[1] = attention_mask: exact causal mask, applied analytically — unused
    const float* cosp = (const float*)d_in[2];
    const float* sinp = (const float*)d_in[3];
    const float* Wq   = (const float*)d_in[4];
    const float* Wk   = (const float*)d_in[5];
    const float* Wv   = (const float*)d_in[6];
    const float* Wo   = (const float*)d_in[7];
    const float* qnw  = (const float*)d_in[8];
    const float* knw  = (const float*)d_in[9];
    float* out = (float*)d_out;

    float *Xr, *QKV, *Qp, *Kp, *VtP, *O, *WqkvT, *WoT;
    cudaGetSymbolAddress((void**)&Xr,    g_X);
    cudaGetSymbolAddress((void**)&QKV,   g_QKV);
    cudaGetSymbolAddress((void**)&Qp,    g_Qp);
    cudaGetSymbolAddress((void**)&Kp,    g_Kp);
    cudaGetSymbolAddress((void**)&VtP,   g_Vt);
    cudaGetSymbolAddress((void**)&O,     g_O);
    cudaGetSymbolAddress((void**)&WqkvT, g_WqkvT);
    cudaGetSymbolAddress((void**)&WoT,   g_WoT);

    cudaFuncSetAttribute(gemm_tf32mma_kernel, cudaFuncAttributeMaxDynamicSharedMemorySize,
                         GM_SMEM_BYTES);
    cudaFuncSetAttribute(flash_tc5_kernel, cudaFuncAttributeMaxDynamicSharedMemorySize,
                         F5_BYTES);

    // X: tf32 round + K-permute; weights: transpose + round + K-permute
    xperm_tf32_kernel<<<2048, 256>>>(Xr, X, (size_t)MROWS * HID / 8);
    transpose_tf32_kernel<<<dim3((NH * DH) / 32, HID / 32), dim3(32, 8)>>>(
        WqkvT, Wq, HID, NH * DH);
    transpose_tf32_kernel<<<dim3((NKV * DH) / 32, HID / 32), dim3(32, 8)>>>(
        WqkvT + (size_t)KOFF * HID, Wk, HID, NKV * DH);
    transpose_tf32_kernel<<<dim3((NKV * DH) / 32, HID / 32), dim3(32, 8)>>>(
        WqkvT + (size_t)VOFF * HID, Wv, HID, NKV * DH);
    transpose_tf32_kernel<<<dim3(HID / 32, (NH * DH) / 32), dim3(32, 8)>>>(
        WoT, Wo, NH * DH, HID);

    // Fused QKV projection (plain epilogue — R11's fused variant regressed)
    gemm_tf32mma_kernel<<<dim3(QKVS / GM_BN, MROWS / GM_BM), 256, GM_SMEM_BYTES>>>(
        Xr, WqkvT, QKV, MROWS, QKVS);

    // RMSNorm + RoPE: Q -> g_Qp (d-permuted, pre-scaled); K -> g_Kp (d-permuted)
    rmsrope_kernel<<<MROWS * NH, 128>>>(QKV, Qp, qnw, cosp, sinp, NH, SCL2E, 0, HID);
    rmsrope_kernel<<<MROWS * NKV, 128>>>(QKV, Kp, knw, cosp, sinp, NKV, 1.0f, KOFF,
                                         NKV * DH);
    vtrans_kernel<<<dim3(S_ / 32, DH / 32, B_ * NKV), dim3(32, 8)>>>(VtP, QKV);

    // Flash attention v5 (BM=256, 512 threads, split-wait single-buffer pipeline)
    flash_tc5_kernel<<<dim3(S_ / 256, NH, B_), 512, F5_BYTES>>>(Qp, Kp, VtP, O);

    // O-projection
    gemm_tf32mma_kernel<<<dim3(HID / GM_BN, MROWS / GM_BM), 256, GM_SMEM_BYTES>>>(
        O, WoT, out, MROWS, HID);
}

// round 14
// speedup vs baseline: 1.0840x; 1.0840x over previous
#include <cuda_runtime.h>
#include <cuda_bf16.h>
#include <math.h>
#include <stdint.h>

// Problem constants
#define B_  2
#define S_  2048
#define HID 2048
#define NH  16
#define NKV 4
#define DH  128
#define MROWS (B_ * S_)        // 4096
#define EPS 1e-6f

// packed QKV col layout: [ Q(0..2047) | K(2048..2559) | V(2560..3071) ]
#define QKVS 3072
#define KOFF 2048
#define VOFF 2560

// 1/sqrt(DH) * log2(e): folded into Q during rmsrope; softmax uses exp2f.
#define SCL2E (0.08838834764831845f * 1.4426950408889634f)

// K-dim fragment interleave: within each 8-group, q -> 2*(q&3) + (q>>2).
__device__ __host__ __forceinline__ int perm8(int q) { return 2 * (q & 3) + (q >> 2); }

// ---------------- scratch ----------------
__device__ float g_X   [(size_t)MROWS * HID];        // Xr (K-permuted input)
__device__ float g_QKV [(size_t)MROWS * QKVS];       // packed Q|K|V (normal layout)
__device__ float g_Qp  [(size_t)MROWS * HID];        // Q, rms+rope'd, d-permuted, prescaled
__device__ float g_Kp  [(size_t)MROWS * NKV * DH];   // K, rms+rope'd, d-permuted
__device__ float g_Vt  [(size_t)B_ * NKV * DH * S_]; // [b][kvh][d][s'], s-permuted, tf32
__device__ float g_O   [(size_t)MROWS * NH * DH];    // flash out, d-permuted
__device__ float g_WqkvT[(size_t)QKVS * HID];        // [N=3072][K=2048], K-permuted
__device__ float g_WoT [(size_t)NH * DH * HID];      // [N=2048][K=2048], K-permuted

// ---------------- helpers ----------------
__device__ __forceinline__ uint32_t smem_u32(const void* p) {
    uint32_t a;
    asm("{ .reg .u64 t; cvta.to.shared.u64 t, %1; cvt.u32.u64 %0, t; }" : "=r"(a) : "l"(p));
    return a;
}
__device__ __forceinline__ float tf32r(float x) {
    uint32_t r;
    asm("cvt.rna.tf32.f32 %0, %1;" : "=r"(r) : "f"(x));
    return __uint_as_float(r);
}
#define CP_ASYNC16(sdst, gsrc) \
    asm volatile("cp.async.cg.shared.global [%0], [%1], 16;" :: "r"(sdst), "l"(gsrc))
#define CP_COMMIT() asm volatile("cp.async.commit_group;" ::: "memory")
#define CP_WAIT(n)  asm volatile("cp.async.wait_group %0;" :: "n"(n) : "memory")

__device__ __forceinline__ void mma_tf32(float& c0, float& c1, float& c2, float& c3,
                                         uint32_t a0, uint32_t a1, uint32_t a2, uint32_t a3,
                                         uint32_t b0, uint32_t b1) {
    asm volatile(
        "mma.sync.aligned.m16n8k8.row.col.f32.tf32.tf32.f32 "
        "{%0,%1,%2,%3}, {%4,%5,%6,%7}, {%8,%9}, {%0,%1,%2,%3};"
        : "+f"(c0), "+f"(c1), "+f"(c2), "+f"(c3)
        : "r"(a0), "r"(a1), "r"(a2), "r"(a3), "r"(b0), "r"(b1));
}

// ---------------- X: tf32 round + K-dim interleave ----------------
__global__ void __launch_bounds__(256) xperm_tf32_kernel(float* __restrict__ dst,
                                                         const float* __restrict__ src,
                                                         size_t n8) {
    for (size_t i = blockIdx.x * blockDim.x + threadIdx.x; i < n8;
         i += (size_t)gridDim.x * blockDim.x) {
        float4 lo = ((const float4*)src)[i * 2];
        float4 hi = ((const float4*)src)[i * 2 + 1];
        float4 o0 = make_float4(tf32r(lo.x), tf32r(hi.x), tf32r(lo.y), tf32r(hi.y));
        float4 o1 = make_float4(tf32r(lo.z), tf32r(hi.z), tf32r(lo.w), tf32r(hi.w));
        ((float4*)dst)[i * 2]     = o0;
        ((float4*)dst)[i * 2 + 1] = o1;
    }
}

// ---------------- ALL weight transposes in one launch (z selects matrix) ----------------
// dst[n][perm(k)] = tf32(src[k][n])
__global__ void __launch_bounds__(256) wtrans_all_kernel(
    float* __restrict__ WqkvT, float* __restrict__ WoT,
    const float* __restrict__ Wq, const float* __restrict__ Wk,
    const float* __restrict__ Wv, const float* __restrict__ Wo)
{
    __shared__ float t[32][33];
    const int z = blockIdx.z;
    const float* src;
    float* dst;
    int R, C;
    if (z == 0)      { src = Wq; dst = WqkvT;                       R = HID;     C = NH * DH; }
    else if (z == 1) { src = Wk; dst = WqkvT + (size_t)KOFF * HID;  R = HID;     C = NKV * DH; }
    else if (z == 2) { src = Wv; dst = WqkvT + (size_t)VOFF * HID;  R = HID;     C = NKV * DH; }
    else             { src = Wo; dst = WoT;                         R = NH * DH; C = HID; }

    int bx = blockIdx.x * 32;
    if (bx >= C) return;
    int by = blockIdx.y * 32;
    int tx = threadIdx.x, ty = threadIdx.y;
#pragma unroll
    for (int i = 0; i < 4; i++)
        t[ty + i * 8][tx] = src[(size_t)(by + ty + i * 8) * C + bx + tx];
    __syncthreads();
    int px = (tx & 24) + perm8(tx & 7);
#pragma unroll
    for (int i = 0; i < 4; i++)
        dst[(size_t)(bx + ty + i * 8) * R + by + px] = tf32r(t[tx][ty + i * 8]);
}

// ---------------- V transpose from packed QKV -> g_Vt [b][kvh][d][s'] (tf32) ----------------
__global__ void __launch_bounds__(256) vtrans_kernel(float* __restrict__ dst,
                                                     const float* __restrict__ src) {
    __shared__ float t[32][33];
    const int bz = blockIdx.z;              // b*NKV + kvh
    const int b = bz >> 2, kvh = bz & 3;
    const int s0 = blockIdx.x * 32, d0 = blockIdx.y * 32;
    const int tx = threadIdx.x, ty = threadIdx.y;   // 32 x 8
#pragma unroll
    for (int i = 0; i < 4; i++)
        t[ty + i * 8][tx] =
            src[(size_t)(b * S_ + s0 + ty + i * 8) * QKVS + VOFF + kvh * DH + d0 + tx];
    __syncthreads();
    int px = (tx & 24) + perm8(tx & 7);
#pragma unroll
    for (int i = 0; i < 4; i++)
        dst[((size_t)bz * DH + d0 + ty + i * 8) * S_ + s0 + px] = tf32r(t[tx][ty + i * 8]);
}

// ---------------- tf32 mma.sync GEMM (K-permuted operands, LDS.64 fragments) ----------------
#define GK      2048
#define GM_BM   128
#define GM_BN   128
#define GM_BK   16
#define GM_LDS  24
#define GM_NST  3
#define GM_NIT  (GK / GM_BK)
#define GM_STAGE_FLOATS (2 * 128 * GM_LDS)   // 6144
#define GM_SMEM_BYTES (GM_NST * GM_STAGE_FLOATS * 4)   // 73728

__device__ __forceinline__ void gm_load_stage(uint32_t sA, uint32_t sB,
                                              const float* __restrict__ Atile,
                                              const float* __restrict__ Btile,
                                              int tid) {
#pragma unroll
    for (int i = 0; i < 2; i++) {
        int idx = i * 256 + tid;
        int r = idx >> 2, c = idx & 3;
        CP_ASYNC16(sA + (uint32_t)(r * (GM_LDS * 4) + c * 16),
                   Atile + (size_t)r * GK + c * 4);
    }
#pragma unroll
    for (int i = 0; i < 2; i++) {
        int idx = i * 256 + tid;
        int r = idx >> 2, c = idx & 3;
        CP_ASYNC16(sB + (uint32_t)(r * (GM_LDS * 4) + c * 16),
                   Btile + (size_t)r * GK + c * 4);
    }
    CP_COMMIT();
}

__global__ void __launch_bounds__(256, 1) gemm_tf32mma_kernel(
    const float* __restrict__ A, const float* __restrict__ Bt,
    float* __restrict__ C, int M, int N)
{
    extern __shared__ float gsm[];
    const uint32_t sbase = smem_u32(gsm);
    const int tid = threadIdx.x;
    const int wid = tid >> 5, lid = tid & 31;
    const int wm = wid >> 1, wn = wid & 1;
    const int gid = lid >> 2, tig = lid & 3;
    const int bm = blockIdx.y * GM_BM;
    const int bn = blockIdx.x * GM_BN;

    float acc[2][8][4];
#pragma unroll
    for (int mt = 0; mt < 2; mt++)
#pragma unroll
        for (int nt = 0; nt < 8; nt++)
#pragma unroll
            for (int q = 0; q < 4; q++) acc[mt][nt][q] = 0.f;

    const float* Abase = A + (size_t)bm * GK;
    const float* Bbase = Bt + (size_t)bn * GK;

    uint32_t stA[GM_NST], stB[GM_NST];
#pragma unroll
    for (int s = 0; s < GM_NST; s++) {
        stA[s] = sbase + (uint32_t)(s * GM_STAGE_FLOATS * 4);
        stB[s] = stA[s] + 128u * GM_LDS * 4u;
    }

    gm_load_stage(stA[0], stB[0], Abase, Bbase, tid);
    gm_load_stage(stA[1], stB[1], Abase + GM_BK, Bbase + GM_BK, tid);

    for (int it = 0; it < GM_NIT; it++) {
        CP_WAIT(1);
        __syncthreads();

        const int ki = it + 2;
        if (ki < GM_NIT) {
            const int b = ki % GM_NST;
            gm_load_stage(stA[b], stB[b], Abase + ki * GM_BK, Bbase + ki * GM_BK, tid);
        }

        const int s = it % GM_NST;
        const float* As0 = gsm + (size_t)s * GM_STAGE_FLOATS;
        const float* Bs0 = As0 + 128 * GM_LDS;

#pragma unroll
        for (int k0 = 0; k0 < GM_BK; k0 += 8) {
            uint32_t af[2][4];
#pragma unroll
            for (int mt = 0; mt < 2; mt++) {
                int r = wm * 32 + mt * 16 + gid;
                float2 aA = *(const float2*)(As0 + r * GM_LDS + k0 + 2 * tig);
                float2 aB = *(const float2*)(As0 + (r + 8) * GM_LDS + k0 + 2 * tig);
                af[mt][0] = __float_as_uint(aA.x);
                af[mt][1] = __float_as_uint(aB.x);
                af[mt][2] = __float_as_uint(aA.y);
                af[mt][3] = __float_as_uint(aB.y);
            }
#pragma unroll
            for (int nt = 0; nt < 8; nt++) {
                int rn = wn * 64 + nt * 8 + gid;
                float2 bv = *(const float2*)(Bs0 + rn * GM_LDS + k0 + 2 * tig);
#pragma unroll
                for (int mt = 0; mt < 2; mt++)
                    mma_tf32(acc[mt][nt][0], acc[mt][nt][1], acc[mt][nt][2], acc[mt][nt][3],
                             af[mt][0], af[mt][1], af[mt][2], af[mt][3],
                             __float_as_uint(bv.x), __float_as_uint(bv.y));
            }
        }
    }

#pragma unroll
    for (int mt = 0; mt < 2; mt++) {
        int r0 = bm + wm * 32 + mt * 16 + gid;
#pragma unroll
        for (int nt = 0; nt < 8; nt++) {
            int c = bn + wn * 64 + nt * 8 + tig * 2;
            *(float2*)(C + (size_t)r0 * N + c) = make_float2(acc[mt][nt][0], acc[mt][nt][1]);
            *(float2*)(C + (size_t)(r0 + 8) * N + c) = make_float2(acc[mt][nt][2], acc[mt][nt][3]);
        }
    }
}

// ---------------- merged RMSNorm + RoPE for Q and K (one launch) ----------------
__global__ void __launch_bounds__(128) rmsrope2_kernel(
    const float* __restrict__ inbuf, float* __restrict__ Qp, float* __restrict__ Kp,
    const float* __restrict__ qnw, const float* __restrict__ knw,
    const float* __restrict__ cosb, const float* __restrict__ sinb)
{
    const int bh = blockIdx.x;
    const bool isQ = bh < MROWS * NH;

    int row, h, in_hoff, ostr;
    const float* w;
    float* outbuf;
    float oscale;
    if (isQ) {
        row = bh >> 4; h = bh & 15;           // NH = 16
        w = qnw; in_hoff = 0; outbuf = Qp; ostr = HID; oscale = SCL2E;
    } else {
        int t = bh - MROWS * NH;
        row = t >> 2; h = t & 3;              // NKV = 4
        w = knw; in_hoff = KOFF; outbuf = Kp; ostr = NKV * DH; oscale = 1.0f;
    }
    const int s = row & (S_ - 1);
    const int d = threadIdx.x;

    const float* p = inbuf + (size_t)row * QKVS + in_hoff + h * DH;
    float v = p[d];

    float ss = v * v;
#pragma unroll
    for (int o = 16; o > 0; o >>= 1) ss += __shfl_xor_sync(0xffffffffu, ss, o);
    __shared__ float sh[4];
    if ((d & 31) == 0) sh[d >> 5] = ss;
    __syncthreads();
    float tot = sh[0] + sh[1] + sh[2] + sh[3];
    float inv = rsqrtf(tot * (1.0f / DH) + EPS);

    int pd = d ^ 64;
    float pv  = p[pd];
    float nv  = w[d]  * v  * inv;
    float npv = w[pd] * pv * inv;
    float c  = cosb[(size_t)s * DH + d];
    float sn = sinb[(size_t)s * DH + d];
    float out = nv * c + ((d < 64) ? -npv : npv) * sn;

    int dp = (d & ~7) + perm8(d & 7);
    outbuf[(size_t)row * ostr + h * DH + dp] = tf32r(out * oscale);
}

// ---------------- tensor-core flash attention v4 (R10 version — best) ----------------
#define FKP 136
#define FVP 72
#define FQ_OFF 0
#define FK_OFF (128 * FKP)
#define FV_OFF (FK_OFF + 2 * 64 * FKP)
#define FT_FLOATS (FV_OFF + 2 * 128 * FVP)
#define FT_BYTES (FT_FLOATS * 4)             // 212992

__global__ void __launch_bounds__(256, 1) flash_tc4_kernel(
    const float* __restrict__ Qp, const float* __restrict__ Kp,
    const float* __restrict__ Vt, float* __restrict__ Og)
{
    extern __shared__ float fsm[];
    const uint32_t sb = smem_u32(fsm);

    const int qt  = (int)gridDim.x - 1 - (int)blockIdx.x;
    const int h   = blockIdx.y;
    const int b   = blockIdx.z;
    const int kvh = h >> 2;
    const int tid = threadIdx.x;
    const int wid = tid >> 5, lid = tid & 31;
    const int gid = lid >> 2, tig = lid & 3;

    const int r1loc = wid * 16 + gid;
    const int r2loc = r1loc + 8;
    const int r1g = qt * 128 + r1loc;
    const int r2g = r1g + 8;

    const float* Kbase  = Kp + (size_t)(b * S_) * (NKV * DH) + (size_t)kvh * DH;
    const float* Vtbase = Vt + ((size_t)(b * NKV + kvh) * DH) * S_;

    {
        const float* Qb = Qp + (size_t)(b * S_ + qt * 128) * HID + (size_t)h * DH;
#pragma unroll
        for (int t = 0; t < 16; t++) {
            int i = tid + t * 256;
            int m = i >> 5, c = i & 31;
            CP_ASYNC16(sb + (uint32_t)((FQ_OFF + m * FKP + c * 4) * 4),
                       Qb + (size_t)m * HID + c * 4);
        }
    }
#pragma unroll
    for (int t = 0; t < 8; t++) {
        int i = tid + t * 256;
        int n = i >> 5, c = i & 31;
        CP_ASYNC16(sb + (uint32_t)((FK_OFF + n * FKP + c * 4) * 4),
                   Kbase + (size_t)n * (NKV * DH) + c * 4);
    }
#pragma unroll
    for (int t = 0; t < 8; t++) {
        int i = tid + t * 256;
        int d = i >> 4, c = i & 15;
        CP_ASYNC16(sb + (uint32_t)((FV_OFF + d * FVP + c * 4) * 4),
                   Vtbase + (size_t)d * S_ + c * 4);
    }
    CP_COMMIT();

    float oacc[16][4];
#pragma unroll
    for (int db = 0; db < 16; db++)
#pragma unroll
        for (int q = 0; q < 4; q++) oacc[db][q] = 0.f;
    float m1 = -1e30f, m2 = -1e30f, l1 = 0.f, l2 = 0.f;

    const int ntiles = 2 * qt + 2;
    for (int j = 0; j < ntiles; j++) {
        CP_WAIT(0);
        __syncthreads();

        if (j + 1 < ntiles) {
            const int nb_ = (j + 1) & 1;
            const uint32_t kd = sb + (uint32_t)((FK_OFF + nb_ * 64 * FKP) * 4);
            const uint32_t vd = sb + (uint32_t)((FV_OFF + nb_ * 128 * FVP) * 4);
#pragma unroll
            for (int t = 0; t < 8; t++) {
                int i = tid + t * 256;
                int n = i >> 5, c = i & 31;
                CP_ASYNC16(kd + (uint32_t)((n * FKP + c * 4) * 4),
                           Kbase + (size_t)((j + 1) * 64 + n) * (NKV * DH) + c * 4);
            }
#pragma unroll
            for (int t = 0; t < 8; t++) {
                int i = tid + t * 256;
                int d = i >> 4, c = i & 15;
                CP_ASYNC16(vd + (uint32_t)((d * FVP + c * 4) * 4),
                           Vtbase + (size_t)d * S_ + (j + 1) * 64 + c * 4);
            }
            CP_COMMIT();
        }

        const float* Qsb = fsm;
        const float* Ksb = fsm + FK_OFF + (j & 1) * 64 * FKP;
        const float* Vsb = fsm + FV_OFF + (j & 1) * 128 * FVP;

        float sacc[8][4];
#pragma unroll
        for (int nb = 0; nb < 8; nb++)
#pragma unroll
            for (int q = 0; q < 4; q++) sacc[nb][q] = 0.f;

#pragma unroll
        for (int ks = 0; ks < 16; ks++) {
            int k0 = ks * 8;
            float2 qa = *(const float2*)(Qsb + r1loc * FKP + k0 + 2 * tig);
            float2 qb = *(const float2*)(Qsb + r2loc * FKP + k0 + 2 * tig);
            uint32_t a0 = __float_as_uint(qa.x);
            uint32_t a1 = __float_as_uint(qb.x);
            uint32_t a2 = __float_as_uint(qa.y);
            uint32_t a3 = __float_as_uint(qb.y);
#pragma unroll
            for (int nb = 0; nb < 8; nb++) {
                float2 kv2 = *(const float2*)(Ksb + (nb * 8 + gid) * FKP + k0 + 2 * tig);
                mma_tf32(sacc[nb][0], sacc[nb][1], sacc[nb][2], sacc[nb][3],
                         a0, a1, a2, a3,
                         __float_as_uint(kv2.x), __float_as_uint(kv2.y));
            }
        }

        if (j >= 2 * qt) {
#pragma unroll
            for (int nb = 0; nb < 8; nb++) {
                int c0g = j * 64 + nb * 8 + tig * 2;
                if (c0g > r1g)     sacc[nb][0] = -1e30f;
                if (c0g + 1 > r1g) sacc[nb][1] = -1e30f;
                if (c0g > r2g)     sacc[nb][2] = -1e30f;
                if (c0g + 1 > r2g) sacc[nb][3] = -1e30f;
            }
        }

        float mx1 = -1e30f, mx2 = -1e30f;
#pragma unroll
        for (int nb = 0; nb < 8; nb++) {
            mx1 = fmaxf(mx1, fmaxf(sacc[nb][0], sacc[nb][1]));
            mx2 = fmaxf(mx2, fmaxf(sacc[nb][2], sacc[nb][3]));
        }
        mx1 = fmaxf(mx1, __shfl_xor_sync(0xffffffffu, mx1, 1));
        mx1 = fmaxf(mx1, __shfl_xor_sync(0xffffffffu, mx1, 2));
        mx2 = fmaxf(mx2, __shfl_xor_sync(0xffffffffu, mx2, 1));
        mx2 = fmaxf(mx2, __shfl_xor_sync(0xffffffffu, mx2, 2));

        float mn1 = fmaxf(m1, mx1), mn2 = fmaxf(m2, mx2);
        const bool changed = (mn1 != m1) | (mn2 != m2);
        const bool any_changed = __any_sync(0xffffffffu, changed);
        float f1 = 1.f, f2 = 1.f;
        if (any_changed) {
            f1 = exp2f(m1 - mn1);
            f2 = exp2f(m2 - mn2);
        }
        m1 = mn1; m2 = mn2;

        float ls1 = 0.f, ls2 = 0.f;
#pragma unroll
        for (int nb = 0; nb < 8; nb++) {
            float p0 = tf32r(exp2f(sacc[nb][0] - mn1));
            float p1 = tf32r(exp2f(sacc[nb][1] - mn1));
            float p2 = tf32r(exp2f(sacc[nb][2] - mn2));
            float p3 = tf32r(exp2f(sacc[nb][3] - mn2));
            sacc[nb][0] = p0; sacc[nb][1] = p1;
            sacc[nb][2] = p2; sacc[nb][3] = p3;
            ls1 += p0 + p1;
            ls2 += p2 + p3;
        }
        ls1 += __shfl_xor_sync(0xffffffffu, ls1, 1);
        ls1 += __shfl_xor_sync(0xffffffffu, ls1, 2);
        ls2 += __shfl_xor_sync(0xffffffffu, ls2, 1);
        ls2 += __shfl_xor_sync(0xffffffffu, ls2, 2);

        if (any_changed) {
            l1 = l1 * f1 + ls1;
            l2 = l2 * f2 + ls2;
#pragma unroll
            for (int db = 0; db < 16; db++) {
                oacc[db][0] *= f1; oacc[db][1] *= f1;
                oacc[db][2] *= f2; oacc[db][3] *= f2;
            }
        } else {
            l1 += ls1;
            l2 += ls2;
        }

        const int s2 = tig >> 1;
        const bool odd = (tig & 1);
#pragma unroll
        for (int ks = 0; ks < 8; ks++) {
            float e, o;
            e = __shfl_sync(0xffffffffu, sacc[ks][0], s2, 4);
            o = __shfl_sync(0xffffffffu, sacc[ks][1], s2, 4);
            float a0f = odd ? o : e;
            e = __shfl_sync(0xffffffffu, sacc[ks][0], s2 + 2, 4);
            o = __shfl_sync(0xffffffffu, sacc[ks][1], s2 + 2, 4);
            float a2f = odd ? o : e;
            e = __shfl_sync(0xffffffffu, sacc[ks][2], s2, 4);
            o = __shfl_sync(0xffffffffu, sacc[ks][3], s2, 4);
            float a1f = odd ? o : e;
            e = __shfl_sync(0xffffffffu, sacc[ks][2], s2 + 2, 4);
            o = __shfl_sync(0xffffffffu, sacc[ks][3], s2 + 2, 4);
            float a3f = odd ? o : e;

            uint32_t a0 = __float_as_uint(a0f);
            uint32_t a1 = __float_as_uint(a1f);
            uint32_t a2 = __float_as_uint(a2f);
            uint32_t a3 = __float_as_uint(a3f);
            int k0 = ks * 8;
#pragma unroll
            for (int db = 0; db < 16; db++) {
                float2 vv = *(const float2*)(Vsb + (db * 8 + gid) * FVP + k0 + 2 * tig);
                mma_tf32(oacc[db][0], oacc[db][1], oacc[db][2], oacc[db][3],
                         a0, a1, a2, a3,
                         __float_as_uint(vv.x), __float_as_uint(vv.y));
            }
        }
    }

    const float inv1 = 1.0f / l1, inv2 = 1.0f / l2;
    const size_t obase = ((size_t)(b * S_ + qt * 128)) * (NH * DH) + (size_t)h * DH;
    const int p0 = perm8(2 * tig);
    const int p1 = perm8(2 * tig + 1);
#pragma unroll
    for (int db = 0; db < 16; db++) {
        float* o1p = Og + obase + (size_t)r1loc * (NH * DH) + db * 8;
        float* o2p = Og + obase + (size_t)r2loc * (NH * DH) + db * 8;
        o1p[p0] = tf32r(oacc[db][0] * inv1);
        o1p[p1] = tf32r(oacc[db][1] * inv1);
        o2p[p0] = tf32r(oacc[db][2] * inv2);
        o2p[p1] = tf32r(oacc[db][3] * inv2);
    }
}

// ---------------- launch ----------------
extern "C" void kernel_launch(void* const* d_in, const int* in_sizes, int n_in,
                              void* d_out, int out_size)
{
    const float* X    = (const float*)d_in[0];
    // d_in[1] = attention_mask: exact causal mask, applied analytically — unused
    const float* cosp = (const float*)d_in[2];
    const float* sinp = (const float*)d_in[3];
    const float* Wq   = (const float*)d_in[4];
    const float* Wk   = (const float*)d_in[5];
    const float* Wv   = (const float*)d_in[6];
    const float* Wo   = (const float*)d_in[7];
    const float* qnw  = (const float*)d_in[8];
    const float* knw  = (const float*)d_in[9];
    float* out = (float*)d_out;

    float *Xr, *QKV, *Qp, *Kp, *VtP, *O, *WqkvT, *WoT;
    cudaGetSymbolAddress((void**)&Xr,    g_X);
    cudaGetSymbolAddress((void**)&QKV,   g_QKV);
    cudaGetSymbolAddress((void**)&Qp,    g_Qp);
    cudaGetSymbolAddress((void**)&Kp,    g_Kp);
    cudaGetSymbolAddress((void**)&VtP,   g_Vt);
    cudaGetSymbolAddress((void**)&O,     g_O);
    cudaGetSymbolAddress((void**)&WqkvT, g_WqkvT);
    cudaGetSymbolAddress((void**)&WoT,   g_WoT);

    cudaFuncSetAttribute(gemm_tf32mma_kernel, cudaFuncAttributeMaxDynamicSharedMemorySize,
                         GM_SMEM_BYTES);
    cudaFuncSetAttribute(flash_tc4_kernel, cudaFuncAttributeMaxDynamicSharedMemorySize,
                         FT_BYTES);

    // launch 1: X round+permute
    xperm_tf32_kernel<<<2048, 256>>>(Xr, X, (size_t)MROWS * HID / 8);
    // launch 2: all 4 weight transposes
    wtrans_all_kernel<<<dim3(HID / 32, HID / 32, 4), dim3(32, 8)>>>(
        WqkvT, WoT, Wq, Wk, Wv, Wo);
    // launch 3: fused QKV projection
    gemm_tf32mma_kernel<<<dim3(QKVS / GM_BN, MROWS / GM_BM), 256, GM_SMEM_BYTES>>>(
        Xr, WqkvT, QKV, MROWS, QKVS);
    // launch 4: RMSNorm + RoPE for Q and K (merged)
    rmsrope2_kernel<<<MROWS * (NH + NKV), 128>>>(QKV, Qp, Kp, qnw, knw, cosp, sinp);
    // launch 5: V transpose
    vtrans_kernel<<<dim3(S_ / 32, DH / 32, B_ * NKV), dim3(32, 8)>>>(VtP, QKV);
    // launch 6: flash attention  (lands on the ncu -s 5 -c 1 slot)
    flash_tc4_kernel<<<dim3(S_ / 128, NH, B_), 256, FT_BYTES>>>(Qp, Kp, VtP, O);
    // launch 7: O-projection
    gemm_tf32mma_kernel<<<dim3(HID / GM_BN, MROWS / GM_BM), 256, GM_SMEM_BYTES>>>(
        O, WoT, out, MROWS, HID);
}

// round 15
// speedup vs baseline: 1.9296x; 1.7802x over previous
#include <cuda_runtime.h>
#include <cuda_fp16.h>
#include <math.h>
#include <stdint.h>

// Problem constants
#define B_  2
#define S_  2048
#define HID 2048
#define NH  16
#define NKV 4
#define DH  128
#define MROWS (B_ * S_)        // 4096
#define EPS 1e-6f

// packed QKV col layout: [ Q(0..2047) | K(2048..2559) | V(2560..3071) ]
#define QKVS 3072
#define KOFF 2048
#define VOFF 2560

// 1/sqrt(DH) * log2(e): folded into Q during rmsrope; softmax uses exp2f.
#define SCL2E (0.08838834764831845f * 1.4426950408889634f)

// K-dim fragment interleave for m16n8k16: within each 16-group,
// logical k -> phys 4*((k>>1)&3) + 2*(k>>3) + (k&1).
// Thread t's LDS.64 at phys 4t..4t+3 then yields logical (2t,2t+1,2t+8,2t+9)
// = exactly (frag_lo, frag_hi) of the fp16 MMA operand.
__device__ __host__ __forceinline__ int p16(int k) {
    return 4 * ((k >> 1) & 3) + 2 * (k >> 3) + (k & 1);
}

// ---------------- scratch ----------------
__device__ __half g_Xh  [(size_t)MROWS * HID];        // X, fp16, k-perm16
__device__ float  g_QKV [(size_t)MROWS * QKVS];       // packed Q|K|V (fp32 GEMM out)
__device__ __half g_Qh  [(size_t)MROWS * HID];        // Q rms+rope'd, d-perm16, prescaled
__device__ __half g_Kh  [(size_t)MROWS * NKV * DH];   // K rms+rope'd, d-perm16
__device__ __half g_Vth [(size_t)B_ * NKV * DH * S_]; // [b][kvh][d][s'], s-perm16
__device__ __half g_Oh  [(size_t)MROWS * NH * DH];    // flash out, d-perm16
__device__ __half g_WqkvTh[(size_t)QKVS * HID];       // [N][K] transposed, k-perm16
__device__ __half g_WoTh [(size_t)NH * DH * HID];

// ---------------- helpers ----------------
__device__ __forceinline__ uint32_t smem_u32(const void* p) {
    uint32_t a;
    asm("{ .reg .u64 t; cvta.to.shared.u64 t, %1; cvt.u32.u64 %0, t; }" : "=r"(a) : "l"(p));
    return a;
}
__device__ __forceinline__ uint32_t h2u(float a, float b) {
    __half2 h = __floats2half2_rn(a, b);
    return *(uint32_t*)&h;
}
#define CP_ASYNC16(sdst, gsrc) \
    asm volatile("cp.async.cg.shared.global [%0], [%1], 16;" :: "r"(sdst), "l"(gsrc))
#define CP_COMMIT() asm volatile("cp.async.commit_group;" ::: "memory")
#define CP_WAIT(n)  asm volatile("cp.async.wait_group %0;" :: "n"(n) : "memory")

__device__ __forceinline__ void mma_f16(float& c0, float& c1, float& c2, float& c3,
                                        uint32_t a0, uint32_t a1, uint32_t a2, uint32_t a3,
                                        uint32_t b0, uint32_t b1) {
    asm volatile(
        "mma.sync.aligned.m16n8k16.row.col.f32.f16.f16.f32 "
        "{%0,%1,%2,%3}, {%4,%5,%6,%7}, {%8,%9}, {%0,%1,%2,%3};"
        : "+f"(c0), "+f"(c1), "+f"(c2), "+f"(c3)
        : "r"(a0), "r"(a1), "r"(a2), "r"(a3), "r"(b0), "r"(b1));
}

// ---------------- X: fp16 convert + k-perm16 (vectorized, 16 floats/thread/iter) ----------
__global__ void __launch_bounds__(256) xperm_h_kernel(__half* __restrict__ dst,
                                                      const float* __restrict__ src,
                                                      size_t n16) {
    for (size_t i = blockIdx.x * blockDim.x + threadIdx.x; i < n16;
         i += (size_t)gridDim.x * blockDim.x) {
        const float4* s = (const float4*)src + i * 4;
        float4 f0 = s[0], f1 = s[1], f2 = s[2], f3 = s[3];
        uint4 o0, o1;
        o0.x = h2u(f0.x, f0.y); o0.y = h2u(f2.x, f2.y);   // phys 0,1<-k0,1  2,3<-k8,9
        o0.z = h2u(f0.z, f0.w); o0.w = h2u(f2.z, f2.w);   // 4,5<-k2,3  6,7<-k10,11
        o1.x = h2u(f1.x, f1.y); o1.y = h2u(f3.x, f3.y);   // 8,9<-k4,5  10,11<-k12,13
        o1.z = h2u(f1.z, f1.w); o1.w = h2u(f3.z, f3.w);   // 12,13<-k6,7  14,15<-k14,15
        ((uint4*)dst)[i * 2]     = o0;
        ((uint4*)dst)[i * 2 + 1] = o1;
    }
}

// ---------------- ALL weight transposes (z selects matrix), fp16 + k-perm16 ----------------
__global__ void __launch_bounds__(256) wtrans_all_kernel(
    __half* __restrict__ WqkvT, __half* __restrict__ WoT,
    const float* __restrict__ Wq, const float* __restrict__ Wk,
    const float* __restrict__ Wv, const float* __restrict__ Wo)
{
    __shared__ float t[32][33];
    const int z = blockIdx.z;
    const float* src;
    __half* dst;
    int R, C;
    if (z == 0)      { src = Wq; dst = WqkvT;                       R = HID;     C = NH * DH; }
    else if (z == 1) { src = Wk; dst = WqkvT + (size_t)KOFF * HID;  R = HID;     C = NKV * DH; }
    else if (z == 2) { src = Wv; dst = WqkvT + (size_t)VOFF * HID;  R = HID;     C = NKV * DH; }
    else             { src = Wo; dst = WoT;                         R = NH * DH; C = HID; }

    int bx = blockIdx.x * 32;
    if (bx >= C) return;
    int by = blockIdx.y * 32;
    int tx = threadIdx.x, ty = threadIdx.y;
#pragma unroll
    for (int i = 0; i < 4; i++)
        t[ty + i * 8][tx] = src[(size_t)(by + ty + i * 8) * C + bx + tx];
    __syncthreads();
    int px = (tx & ~15) + p16(tx & 15);
#pragma unroll
    for (int i = 0; i < 4; i++)
        dst[(size_t)(bx + ty + i * 8) * R + by + px] = __float2half_rn(t[tx][ty + i * 8]);
}

// ---------------- V transpose: QKV fp32 -> g_Vth [b][kvh][d][s'] fp16, s-perm16 ------------
__global__ void __launch_bounds__(256) vtrans_kernel(__half* __restrict__ dst,
                                                     const float* __restrict__ src) {
    __shared__ float t[32][33];
    const int bz = blockIdx.z;              // b*NKV + kvh
    const int b = bz >> 2, kvh = bz & 3;
    const int s0 = blockIdx.x * 32, d0 = blockIdx.y * 32;
    const int tx = threadIdx.x, ty = threadIdx.y;
#pragma unroll
    for (int i = 0; i < 4; i++)
        t[ty + i * 8][tx] =
            src[(size_t)(b * S_ + s0 + ty + i * 8) * QKVS + VOFF + kvh * DH + d0 + tx];
    __syncthreads();
    int px = (tx & ~15) + p16(tx & 15);
#pragma unroll
    for (int i = 0; i < 4; i++)
        dst[((size_t)bz * DH + d0 + ty + i * 8) * S_ + s0 + px] =
            __float2half_rn(t[tx][ty + i * 8]);
}

// ---------------- fp16 mma.sync GEMM: C[M,N](f32) = A[M,2048]h @ Bt[N,2048]h^T ------------
#define GK      2048
#define GM_BKH  32                            // halves per iter (2 x k16)
#define GM_LDSH 48                            // smem stride in halves (96B; mod 128B = 96)
#define GM_NST  3
#define GM_NIT  (GK / GM_BKH)                 // 64
#define GM_STAGE_HALVES (2 * 128 * GM_LDSH)   // 12288
#define GM_SMEM_BYTES (GM_NST * GM_STAGE_HALVES * 2)   // 73728

__device__ __forceinline__ void gm_load_stage(uint32_t sA, uint32_t sB,
                                              const __half* __restrict__ Atile,
                                              const __half* __restrict__ Btile,
                                              int tid) {
#pragma unroll
    for (int i = 0; i < 2; i++) {            // A: 128 rows x 4 chunks (16B = 8 halves)
        int idx = i * 256 + tid;
        int r = idx >> 2, c = idx & 3;
        CP_ASYNC16(sA + (uint32_t)(r * (GM_LDSH * 2) + c * 16),
                   Atile + (size_t)r * GK + c * 8);
    }
#pragma unroll
    for (int i = 0; i < 2; i++) {
        int idx = i * 256 + tid;
        int r = idx >> 2, c = idx & 3;
        CP_ASYNC16(sB + (uint32_t)(r * (GM_LDSH * 2) + c * 16),
                   Btile + (size_t)r * GK + c * 8);
    }
    CP_COMMIT();
}

__global__ void __launch_bounds__(256, 1) gemm_f16_kernel(
    const __half* __restrict__ A, const __half* __restrict__ Bt,
    float* __restrict__ C, int M, int N)
{
    extern __shared__ __half gsmh[];
    const uint32_t sbase = smem_u32(gsmh);
    const int tid = threadIdx.x;
    const int wid = tid >> 5, lid = tid & 31;
    const int wm = wid >> 1, wn = wid & 1;
    const int gid = lid >> 2, tig = lid & 3;
    const int bm = blockIdx.y * 128;
    const int bn = blockIdx.x * 128;

    float acc[2][8][4];
#pragma unroll
    for (int mt = 0; mt < 2; mt++)
#pragma unroll
        for (int nt = 0; nt < 8; nt++)
#pragma unroll
            for (int q = 0; q < 4; q++) acc[mt][nt][q] = 0.f;

    const __half* Abase = A + (size_t)bm * GK;
    const __half* Bbase = Bt + (size_t)bn * GK;

    uint32_t stA[GM_NST], stB[GM_NST];
#pragma unroll
    for (int s = 0; s < GM_NST; s++) {
        stA[s] = sbase + (uint32_t)(s * GM_STAGE_HALVES * 2);
        stB[s] = stA[s] + 128u * GM_LDSH * 2u;
    }

    gm_load_stage(stA[0], stB[0], Abase, Bbase, tid);
    gm_load_stage(stA[1], stB[1], Abase + GM_BKH, Bbase + GM_BKH, tid);

    for (int it = 0; it < GM_NIT; it++) {
        CP_WAIT(1);
        __syncthreads();

        const int ki = it + 2;
        if (ki < GM_NIT) {
            const int b = ki % GM_NST;
            gm_load_stage(stA[b], stB[b], Abase + ki * GM_BKH, Bbase + ki * GM_BKH, tid);
        }

        const int s = it % GM_NST;
        const __half* As0 = gsmh + (size_t)s * GM_STAGE_HALVES;
        const __half* Bs0 = As0 + 128 * GM_LDSH;

#pragma unroll
        for (int kk = 0; kk < 2; kk++) {
            const int kh = kk * 16 + 4 * tig;
            uint32_t af[2][4];
#pragma unroll
            for (int mt = 0; mt < 2; mt++) {
                int r = wm * 32 + mt * 16 + gid;
                uint2 aA = *(const uint2*)(As0 + r * GM_LDSH + kh);
                uint2 aB = *(const uint2*)(As0 + (r + 8) * GM_LDSH + kh);
                af[mt][0] = aA.x; af[mt][1] = aB.x;
                af[mt][2] = aA.y; af[mt][3] = aB.y;
            }
#pragma unroll
            for (int nt = 0; nt < 8; nt++) {
                int rn = wn * 64 + nt * 8 + gid;
                uint2 bv = *(const uint2*)(Bs0 + rn * GM_LDSH + kh);
#pragma unroll
                for (int mt = 0; mt < 2; mt++)
                    mma_f16(acc[mt][nt][0], acc[mt][nt][1], acc[mt][nt][2], acc[mt][nt][3],
                            af[mt][0], af[mt][1], af[mt][2], af[mt][3], bv.x, bv.y);
            }
        }
    }

#pragma unroll
    for (int mt = 0; mt < 2; mt++) {
        int r0 = bm + wm * 32 + mt * 16 + gid;
#pragma unroll
        for (int nt = 0; nt < 8; nt++) {
            int c = bn + wn * 64 + nt * 8 + tig * 2;
            *(float2*)(C + (size_t)r0 * N + c) = make_float2(acc[mt][nt][0], acc[mt][nt][1]);
            *(float2*)(C + (size_t)(r0 + 8) * N + c) = make_float2(acc[mt][nt][2], acc[mt][nt][3]);
        }
    }
}

// ---------------- merged RMSNorm + RoPE for Q and K -> fp16, d-perm16 ----------------
__global__ void __launch_bounds__(128) rmsrope2_kernel(
    const float* __restrict__ inbuf, __half* __restrict__ Qh, __half* __restrict__ Kh,
    const float* __restrict__ qnw, const float* __restrict__ knw,
    const float* __restrict__ cosb, const float* __restrict__ sinb)
{
    const int bh = blockIdx.x;
    const bool isQ = bh < MROWS * NH;

    int row, h, in_hoff, ostr;
    const float* w;
    __half* outbuf;
    float oscale;
    if (isQ) {
        row = bh >> 4; h = bh & 15;
        w = qnw; in_hoff = 0; outbuf = Qh; ostr = HID; oscale = SCL2E;
    } else {
        int t = bh - MROWS * NH;
        row = t >> 2; h = t & 3;
        w = knw; in_hoff = KOFF; outbuf = Kh; ostr = NKV * DH; oscale = 1.0f;
    }
    const int s = row & (S_ - 1);
    const int d = threadIdx.x;

    const float* p = inbuf + (size_t)row * QKVS + in_hoff + h * DH;
    float v = p[d];

    float ss = v * v;
#pragma unroll
    for (int o = 16; o > 0; o >>= 1) ss += __shfl_xor_sync(0xffffffffu, ss, o);
    __shared__ float sh[4];
    if ((d & 31) == 0) sh[d >> 5] = ss;
    __syncthreads();
    float tot = sh[0] + sh[1] + sh[2] + sh[3];
    float inv = rsqrtf(tot * (1.0f / DH) + EPS);

    int pd = d ^ 64;
    float pv  = p[pd];
    float nv  = w[d]  * v  * inv;
    float npv = w[pd] * pv * inv;
    float c  = cosb[(size_t)s * DH + d];
    float sn = sinb[(size_t)s * DH + d];
    float out = nv * c + ((d < 64) ? -npv : npv) * sn;

    int dp = (d & ~15) + p16(d & 15);
    outbuf[(size_t)row * ostr + h * DH + dp] = __float2half_rn(out * oscale);
}

// ---------------- fp16 tensor-core flash attention ----------------
// BM=128 q rows, BN=64 kv cols, 256 threads = 8 warps x 16 rows.
// All operands fp16 perm16; softmax fp32; PV A-frag = own sacc registers (no shfl).
#define FH_QS 144                              // half stride (288B; mod 128B = 32)
#define FH_VSS 80                              // V stride (160B; mod 128B = 32)
#define FH_KOFF (128 * FH_QS)                  // 18432 halves
#define FH_VOFF (FH_KOFF + 2 * 64 * FH_QS)     // 36864
#define FH_HALVES (FH_VOFF + 2 * 128 * FH_VSS) // 57344
#define FH_BYTES (FH_HALVES * 2)               // 114688

__global__ void __launch_bounds__(256, 1) flash_h_kernel(
    const __half* __restrict__ Qp, const __half* __restrict__ Kp,
    const __half* __restrict__ Vt, __half* __restrict__ Og)
{
    extern __shared__ __half fsmh[];
    const uint32_t sb = smem_u32(fsmh);

    const int qt  = (int)gridDim.x - 1 - (int)blockIdx.x;
    const int h   = blockIdx.y;
    const int b   = blockIdx.z;
    const int kvh = h >> 2;
    const int tid = threadIdx.x;
    const int wid = tid >> 5, lid = tid & 31;
    const int gid = lid >> 2, tig = lid & 3;

    const int r1loc = wid * 16 + gid;
    const int r2loc = r1loc + 8;
    const int r1g = qt * 128 + r1loc;
    const int r2g = r1g + 8;

    const __half* Kbase  = Kp + (size_t)(b * S_) * (NKV * DH) + (size_t)kvh * DH;
    const __half* Vtbase = Vt + ((size_t)(b * NKV + kvh) * DH) * S_;

    // Q tile: 128 rows x 16 chunks (16B = 8 halves)
    {
        const __half* Qb = Qp + (size_t)(b * S_ + qt * 128) * HID + (size_t)h * DH;
#pragma unroll
        for (int t = 0; t < 8; t++) {
            int i = tid + t * 256;
            int m = i >> 4, c = i & 15;
            CP_ASYNC16(sb + (uint32_t)((m * FH_QS + c * 8) * 2),
                       Qb + (size_t)m * HID + c * 8);
        }
    }
    // K tile 0: 64 rows x 16 chunks
#pragma unroll
    for (int t = 0; t < 4; t++) {
        int i = tid + t * 256;
        int n = i >> 4, c = i & 15;
        CP_ASYNC16(sb + (uint32_t)((FH_KOFF + n * FH_QS + c * 8) * 2),
                   Kbase + (size_t)n * (NKV * DH) + c * 8);
    }
    // V tile 0: 128 d-rows x 8 chunks
#pragma unroll
    for (int t = 0; t < 4; t++) {
        int i = tid + t * 256;
        int d = i >> 3, c = i & 7;
        CP_ASYNC16(sb + (uint32_t)((FH_VOFF + d * FH_VSS + c * 8) * 2),
                   Vtbase + (size_t)d * S_ + c * 8);
    }
    CP_COMMIT();

    float oacc[16][4];
#pragma unroll
    for (int db = 0; db < 16; db++)
#pragma unroll
        for (int q = 0; q < 4; q++) oacc[db][q] = 0.f;
    float m1 = -1e30f, m2 = -1e30f, l1 = 0.f, l2 = 0.f;

    const int ntiles = 2 * qt + 2;
    for (int j = 0; j < ntiles; j++) {
        CP_WAIT(0);
        __syncthreads();

        if (j + 1 < ntiles) {
            const int nb_ = (j + 1) & 1;
            const uint32_t kd = sb + (uint32_t)((FH_KOFF + nb_ * 64 * FH_QS) * 2);
            const uint32_t vd = sb + (uint32_t)((FH_VOFF + nb_ * 128 * FH_VSS) * 2);
#pragma unroll
            for (int t = 0; t < 4; t++) {
                int i = tid + t * 256;
                int n = i >> 4, c = i & 15;
                CP_ASYNC16(kd + (uint32_t)((n * FH_QS + c * 8) * 2),
                           Kbase + (size_t)((j + 1) * 64 + n) * (NKV * DH) + c * 8);
            }
#pragma unroll
            for (int t = 0; t < 4; t++) {
                int i = tid + t * 256;
                int d = i >> 3, c = i & 7;
                CP_ASYNC16(vd + (uint32_t)((d * FH_VSS + c * 8) * 2),
                           Vtbase + (size_t)d * S_ + (j + 1) * 64 + c * 8);
            }
            CP_COMMIT();
        }

        const __half* Qsb = fsmh;
        const __half* Ksb = fsmh + FH_KOFF + (j & 1) * 64 * FH_QS;
        const __half* Vsb = fsmh + FH_VOFF + (j & 1) * 128 * FH_VSS;

        // S = Q @ K^T : 8 k16-steps
        float sacc[8][4];
#pragma unroll
        for (int nb = 0; nb < 8; nb++)
#pragma unroll
            for (int q = 0; q < 4; q++) sacc[nb][q] = 0.f;

#pragma unroll
        for (int ks = 0; ks < 8; ks++) {
            const int kh = ks * 16 + 4 * tig;
            uint2 qa = *(const uint2*)(Qsb + r1loc * FH_QS + kh);
            uint2 qb = *(const uint2*)(Qsb + r2loc * FH_QS + kh);
#pragma unroll
            for (int nb = 0; nb < 8; nb++) {
                uint2 kv = *(const uint2*)(Ksb + (nb * 8 + gid) * FH_QS + kh);
                mma_f16(sacc[nb][0], sacc[nb][1], sacc[nb][2], sacc[nb][3],
                        qa.x, qb.x, qa.y, qb.y, kv.x, kv.y);
            }
        }

        // causal mask
        if (j >= 2 * qt) {
#pragma unroll
            for (int nb = 0; nb < 8; nb++) {
                int c0g = j * 64 + nb * 8 + tig * 2;
                if (c0g > r1g)     sacc[nb][0] = -1e30f;
                if (c0g + 1 > r1g) sacc[nb][1] = -1e30f;
                if (c0g > r2g)     sacc[nb][2] = -1e30f;
                if (c0g + 1 > r2g) sacc[nb][3] = -1e30f;
            }
        }

        // row max over quad
        float mx1 = -1e30f, mx2 = -1e30f;
#pragma unroll
        for (int nb = 0; nb < 8; nb++) {
            mx1 = fmaxf(mx1, fmaxf(sacc[nb][0], sacc[nb][1]));
            mx2 = fmaxf(mx2, fmaxf(sacc[nb][2], sacc[nb][3]));
        }
        mx1 = fmaxf(mx1, __shfl_xor_sync(0xffffffffu, mx1, 1));
        mx1 = fmaxf(mx1, __shfl_xor_sync(0xffffffffu, mx1, 2));
        mx2 = fmaxf(mx2, __shfl_xor_sync(0xffffffffu, mx2, 1));
        mx2 = fmaxf(mx2, __shfl_xor_sync(0xffffffffu, mx2, 2));

        float mn1 = fmaxf(m1, mx1), mn2 = fmaxf(m2, mx2);
        const bool changed = (mn1 != m1) | (mn2 != m2);
        const bool any_changed = __any_sync(0xffffffffu, changed);
        float f1 = 1.f, f2 = 1.f;
        if (any_changed) {
            f1 = exp2f(m1 - mn1);
            f2 = exp2f(m2 - mn2);
        }
        m1 = mn1; m2 = mn2;

        // probs (fp32 in sacc; fp16 rounding happens at PV packing) + row sums
        float ls1 = 0.f, ls2 = 0.f;
#pragma unroll
        for (int nb = 0; nb < 8; nb++) {
            float p0 = exp2f(sacc[nb][0] - mn1);
            float p1 = exp2f(sacc[nb][1] - mn1);
            float p2 = exp2f(sacc[nb][2] - mn2);
            float p3 = exp2f(sacc[nb][3] - mn2);
            sacc[nb][0] = p0; sacc[nb][1] = p1;
            sacc[nb][2] = p2; sacc[nb][3] = p3;
            ls1 += p0 + p1;
            ls2 += p2 + p3;
        }
        ls1 += __shfl_xor_sync(0xffffffffu, ls1, 1);
        ls1 += __shfl_xor_sync(0xffffffffu, ls1, 2);
        ls2 += __shfl_xor_sync(0xffffffffu, ls2, 1);
        ls2 += __shfl_xor_sync(0xffffffffu, ls2, 2);

        if (any_changed) {
            l1 = l1 * f1 + ls1;
            l2 = l2 * f2 + ls2;
#pragma unroll
            for (int db = 0; db < 16; db++) {
                oacc[db][0] *= f1; oacc[db][1] *= f1;
                oacc[db][2] *= f2; oacc[db][3] *= f2;
            }
        } else {
            l1 += ls1;
            l2 += ls2;
        }

        // O += P @ V : 4 k16-steps; A-frag = own sacc registers packed to half2
#pragma unroll
        for (int ks = 0; ks < 4; ks++) {
            uint32_t a0 = h2u(sacc[2 * ks][0],     sacc[2 * ks][1]);
            uint32_t a1 = h2u(sacc[2 * ks][2],     sacc[2 * ks][3]);
            uint32_t a2 = h2u(sacc[2 * ks + 1][0], sacc[2 * ks + 1][1]);
            uint32_t a3 = h2u(sacc[2 * ks + 1][2], sacc[2 * ks + 1][3]);
            const int kh = ks * 16 + 4 * tig;
#pragma unroll
            for (int db = 0; db < 16; db++) {
                uint2 vv = *(const uint2*)(Vsb + (db * 8 + gid) * FH_VSS + kh);
                mma_f16(oacc[db][0], oacc[db][1], oacc[db][2], oacc[db][3],
                        a0, a1, a2, a3, vv.x, vv.y);
            }
        }
    }

    // epilogue: normalize, fp16-round, write d-perm16 (feeds fp16 O-proj)
    const float inv1 = 1.0f / l1, inv2 = 1.0f / l2;
    const size_t obase = ((size_t)(b * S_ + qt * 128)) * (NH * DH) + (size_t)h * DH;
#pragma unroll
    for (int db = 0; db < 16; db++) {
        int c = db * 8 + 2 * tig;
        int loc = c & 15;
        int p = (c & ~15) + 4 * ((loc >> 1) & 3) + 2 * (loc >> 3);   // p16(even); p+1 = odd
        __half2 v1 = __floats2half2_rn(oacc[db][0] * inv1, oacc[db][1] * inv1);
        __half2 v2 = __floats2half2_rn(oacc[db][2] * inv2, oacc[db][3] * inv2);
        *(__half2*)(Og + obase + (size_t)r1loc * (NH * DH) + p) = v1;
        *(__half2*)(Og + obase + (size_t)r2loc * (NH * DH) + p) = v2;
    }
}

// ---------------- launch ----------------
extern "C" void kernel_launch(void* const* d_in, const int* in_sizes, int n_in,
                              void* d_out, int out_size)
{
    const float* X    = (const float*)d_in[0];
    // d_in[1] = attention_mask: exact causal mask, applied analytically — unused
    const float* cosp = (const float*)d_in[2];
    const float* sinp = (const float*)d_in[3];
    const float* Wq   = (const float*)d_in[4];
    const float* Wk   = (const float*)d_in[5];
    const float* Wv   = (const float*)d_in[6];
    const float* Wo   = (const float*)d_in[7];
    const float* qnw  = (const float*)d_in[8];
    const float* knw  = (const float*)d_in[9];
    float* out = (float*)d_out;

    __half *Xh, *Qh, *Kh, *Vth, *Oh, *WqkvTh, *WoTh;
    float *QKV;
    cudaGetSymbolAddress((void**)&Xh,     g_Xh);
    cudaGetSymbolAddress((void**)&QKV,    g_QKV);
    cudaGetSymbolAddress((void**)&Qh,     g_Qh);
    cudaGetSymbolAddress((void**)&Kh,     g_Kh);
    cudaGetSymbolAddress((void**)&Vth,    g_Vth);
    cudaGetSymbolAddress((void**)&Oh,     g_Oh);
    cudaGetSymbolAddress((void**)&WqkvTh, g_WqkvTh);
    cudaGetSymbolAddress((void**)&WoTh,   g_WoTh);

    cudaFuncSetAttribute(gemm_f16_kernel, cudaFuncAttributeMaxDynamicSharedMemorySize,
                         GM_SMEM_BYTES);
    cudaFuncSetAttribute(flash_h_kernel, cudaFuncAttributeMaxDynamicSharedMemorySize,
                         FH_BYTES);

    // launch 1: X fp16 convert + perm16
    xperm_h_kernel<<<2048, 256>>>(Xh, X, (size_t)MROWS * HID / 16);
    // launch 2: all weight transposes (fp16 + perm16)
    wtrans_all_kernel<<<dim3(HID / 32, HID / 32, 4), dim3(32, 8)>>>(
        WqkvTh, WoTh, Wq, Wk, Wv, Wo);
    // launch 3: fused QKV projection (fp16 MMA, fp32 out)
    gemm_f16_kernel<<<dim3(QKVS / 128, MROWS / 128), 256, GM_SMEM_BYTES>>>(
        Xh, WqkvTh, QKV, MROWS, QKVS);
    // launch 4: RMSNorm + RoPE (Q and K merged) -> fp16
    rmsrope2_kernel<<<MROWS * (NH + NKV), 128>>>(QKV, Qh, Kh, qnw, knw, cosp, sinp);
    // launch 5: V transpose -> fp16
    vtrans_kernel<<<dim3(S_ / 32, DH / 32, B_ * NKV), dim3(32, 8)>>>(Vth, QKV);
    // launch 6: flash attention (fp16)
    flash_h_kernel<<<dim3(S_ / 128, NH, B_), 256, FH_BYTES>>>(Qh, Kh, Vth, Oh);
    // launch 7: O-projection (fp16 MMA, fp32 out)
    gemm_f16_kernel<<<dim3(HID / 128, MROWS / 128), 256, GM_SMEM_BYTES>>>(
        Oh, WoTh, out, MROWS, HID);
}